// round 13
// baseline (speedup 1.0000x reference)
#include <cuda_runtime.h>
#include <cuda_bf16.h>
#include <cstdint>

#define NNODES 50000
#define NEDGES 400000
#define DIM 512
#define NLAYERS 4
#define NGRAPHS 500
#define OUTD 2048
#define EPSF 1e-5f
#define NEG 0.01f

// ---------------- scratch ----------------
__device__ float g_bufA[(size_t)NNODES * DIM];
__device__ __nv_bfloat16 g_hi[(size_t)NNODES * DIM];    // GEMM1 input (from aggregate)
__device__ __nv_bfloat16 g_lo[(size_t)NNODES * DIM];
__device__ __nv_bfloat16 g_hi2[(size_t)NNODES * DIM];   // GEMM1 output / GEMM2 input
__device__ __nv_bfloat16 g_lo2[(size_t)NNODES * DIM];
__device__ __nv_bfloat16 g_wt1h[NLAYERS * DIM * DIM], g_wt1l[NLAYERS * DIM * DIM];
__device__ __nv_bfloat16 g_wt2h[NLAYERS * DIM * DIM], g_wt2l[NLAYERS * DIM * DIM];
__device__ int   g_off[NNODES + 1];
__device__ int   g_cur[NNODES];
__device__ int   g_esrc[NEDGES];
__device__ float g_colps[64 * DIM];      // per-rowblock col partial sums
__device__ float g_colpq[64 * DIM];      // per-rowblock col partial sumsq
__device__ float g_rowmean[NNODES];
__device__ float g_rowinv[NNODES];
__device__ float g_scale[DIM];
__device__ float g_shift[DIM];
__device__ int   g_gstart[NGRAPHS + 1];

__device__ __forceinline__ uint32_t smem_u32(const void* p) {
    uint32_t a;
    asm("{ .reg .u64 t; cvta.to.shared.u64 t, %1; cvt.u32.u64 %0, t; }" : "=r"(a) : "l"(p));
    return a;
}

#define LDMX4(r0, r1, r2, r3, addr) \
    asm volatile("ldmatrix.sync.aligned.m8n8.x4.shared.b16 {%0,%1,%2,%3}, [%4];" \
        : "=r"(r0), "=r"(r1), "=r"(r2), "=r"(r3) : "r"(addr))

#define MMA16816(d, a0, a1, a2, a3, b0, b1) \
    asm volatile("mma.sync.aligned.m16n8k16.row.col.f32.bf16.bf16.f32 " \
        "{%0,%1,%2,%3}, {%4,%5,%6,%7}, {%8,%9}, {%0,%1,%2,%3};" \
        : "+f"((d)[0]), "+f"((d)[1]), "+f"((d)[2]), "+f"((d)[3]) \
        : "r"(a0), "r"(a1), "r"(a2), "r"(a3), "r"(b0), "r"(b1))

__device__ __forceinline__ void cp16z(uint32_t dst, const void* src, int srcsize) {
    asm volatile("cp.async.cg.shared.global [%0], [%1], 16, %2;" :: "r"(dst), "l"(src), "r"(srcsize));
}
__device__ __forceinline__ void cp16(uint32_t dst, const void* src) {
    asm volatile("cp.async.cg.shared.global [%0], [%1], 16;" :: "r"(dst), "l"(src));
}
#define CP_COMMIT() asm volatile("cp.async.commit_group;")

__device__ __forceinline__ __nv_bfloat162 pk2(float a, float b) {
    __nv_bfloat162 r; r.x = __float2bfloat16(a); r.y = __float2bfloat16(b); return r;
}

// ---------------- weights conversion + g_cur zeroing (launch #1) ----------------
__global__ void k_wconv_all(const float* __restrict__ W1, const float* __restrict__ W2) {
    int gb = (blockIdx.z * gridDim.y + blockIdx.y) * gridDim.x + blockIdx.x;
    int gidx = gb * 1024 + threadIdx.y * 32 + threadIdx.x;
    if (gidx < NNODES) g_cur[gidx] = 0;

    __shared__ float tile[32][33];
    int zc = blockIdx.z;
    int l = zc >> 1, which = zc & 1;
    const float* W = ((which == 0) ? W1 : W2) + (size_t)l * DIM * DIM;
    int k0 = blockIdx.y * 32, n0 = blockIdx.x * 32;
    int tx = threadIdx.x, ty = threadIdx.y;
    tile[ty][tx] = W[(size_t)(k0 + ty) * DIM + n0 + tx];
    __syncthreads();
    float v = tile[tx][ty];
    __nv_bfloat16 h = __float2bfloat16(v);
    float lo = v - __bfloat162float(h);
    size_t idx = (size_t)l * DIM * DIM + (size_t)(n0 + ty) * DIM + k0 + tx;
    if (which == 0) { g_wt1h[idx] = h; g_wt1l[idx] = __float2bfloat16(lo); }
    else            { g_wt2h[idx] = h; g_wt2l[idx] = __float2bfloat16(lo); }
}

// ---------------- CSR build ----------------
__global__ void k_count(const int* __restrict__ ei) {
    int e = blockIdx.x * blockDim.x + threadIdx.x;
    if (e < NEDGES) atomicAdd(&g_cur[ei[NEDGES + e]], 1);
}
__global__ void k_scan() {
    __shared__ int wsum[32];
    __shared__ int carry_s;
    int tid = threadIdx.x, lane = tid & 31, wid = tid >> 5;
    if (tid == 0) carry_s = 0;
    __syncthreads();
    for (int base = 0; base < NNODES; base += 1024) {
        int i = base + tid;
        int orig = (i < NNODES) ? g_cur[i] : 0;
        int v = orig;
        #pragma unroll
        for (int o = 1; o < 32; o <<= 1) {
            int t = __shfl_up_sync(0xffffffffu, v, o);
            if (lane >= o) v += t;
        }
        if (lane == 31) wsum[wid] = v;
        __syncthreads();
        if (wid == 0) {
            int s = wsum[lane];
            #pragma unroll
            for (int o = 1; o < 32; o <<= 1) {
                int t = __shfl_up_sync(0xffffffffu, s, o);
                if (lane >= o) s += t;
            }
            wsum[lane] = s;
        }
        __syncthreads();
        int prev = (wid > 0) ? wsum[wid - 1] : 0;
        int incl = carry_s + prev + v;
        int excl = incl - orig;
        if (i < NNODES) { g_off[i] = excl; g_cur[i] = excl; }
        __syncthreads();
        if (tid == 1023) carry_s = incl;
        __syncthreads();
    }
    if (threadIdx.x == 0) g_off[NNODES] = carry_s;
}
__global__ void k_fill(const int* __restrict__ ei) {
    int e = blockIdx.x * blockDim.x + threadIdx.x;
    if (e < NEDGES) {
        int p = atomicAdd(&g_cur[ei[NEDGES + e]], 1);
        g_esrc[p] = ei[e];
    }
}
__global__ void k_gstart(const int* __restrict__ batch) {
    int g = blockIdx.x * blockDim.x + threadIdx.x;
    if (g > NGRAPHS) return;
    int lo = 0, hi = NNODES;
    while (lo < hi) {
        int mid = (lo + hi) >> 1;
        if (batch[mid] < g) lo = mid + 1; else hi = mid;
    }
    g_gstart[g] = lo;
}

// ---------------- aggregation -> split bf16 into g_hi/g_lo ----------------
__global__ void k_aggregate(const float* __restrict__ h, int ldh) {
    int n = blockIdx.x;
    int t = threadIdx.x;   // 128 threads * 4 cols
    float4 acc = __ldg((const float4*)(h + (size_t)n * ldh) + t);
    int e0 = g_off[n], e1 = g_off[n + 1];
    for (int e = e0; e < e1; ++e) {
        int s = g_esrc[e];
        float4 v = __ldg((const float4*)(h + (size_t)s * ldh) + t);
        acc.x += v.x; acc.y += v.y; acc.z += v.z; acc.w += v.w;
    }
    __nv_bfloat162 h01 = pk2(acc.x, acc.y), h23 = pk2(acc.z, acc.w);
    float lx = acc.x - __bfloat162float(h01.x);
    float ly = acc.y - __bfloat162float(h01.y);
    float lz = acc.z - __bfloat162float(h23.x);
    float lw = acc.w - __bfloat162float(h23.y);
    __nv_bfloat162* hp = (__nv_bfloat162*)(g_hi + (size_t)n * DIM);
    __nv_bfloat162* lp = (__nv_bfloat162*)(g_lo + (size_t)n * DIM);
    hp[2 * t] = h01; hp[2 * t + 1] = h23;
    lp[2 * t] = pk2(lx, ly); lp[2 * t + 1] = pk2(lz, lw);
}

// ---------------- mma.sync GEMM (byte-identical to round-12 passing version) ----------
#define TILE_BYTES 10240          // 128*40*2
#define STAGE_BYTES 40960
#define SMEM_TOTAL 81920

template <int MODE>
__global__ void __launch_bounds__(256, 2) k_mma(int layer, const float* __restrict__ bias, int M) {
    extern __shared__ char smem[];
    uint32_t sb = smem_u32(smem);

    size_t wo = (size_t)layer * DIM * DIM;
    const __nv_bfloat16* AH = (MODE == 0) ? g_hi : g_hi2;
    const __nv_bfloat16* AL = (MODE == 0) ? g_lo : g_lo2;
    const __nv_bfloat16* WH = ((MODE == 0) ? g_wt1h : g_wt2h) + wo;
    const __nv_bfloat16* WL = ((MODE == 0) ? g_wt1l : g_wt2l) + wo;

    int tid  = threadIdx.x;
    int lane = tid & 31;
    int wid  = tid >> 5;
    int wm   = wid & 3;
    int wn   = wid >> 2;
    int bm   = blockIdx.y * 128;
    int bn   = blockIdx.x * 128;

    float acc[2][8][4];
    #pragma unroll
    for (int i = 0; i < 2; ++i)
        #pragma unroll
        for (int j = 0; j < 8; ++j)
            #pragma unroll
            for (int q = 0; q < 4; ++q) acc[i][j][q] = 0.f;

    int lrow = tid >> 1;
    int lseg = (tid & 1) * 2;

    int a_r = (lane & 7) + ((lane >> 3) & 1) * 8;
    int a_c = (lane >> 4) * 8;
    int b_r = (lane & 7) + (lane >> 4) * 8;
    int b_c = ((lane >> 3) & 1) * 8;

    int gr = bm + lrow;
    int asz = (gr < M) ? 16 : 0;
    int grc = (gr < M) ? gr : (M - 1);
    int brow = bn + lrow;

    auto stage_load = [&](int kt, int s) {
        int k0 = kt * 32;
        uint32_t base = sb + s * STAGE_BYTES;
        #pragma unroll
        for (int j = 0; j < 2; ++j) {
            int seg = lseg + j;
            uint32_t soff = (uint32_t)(lrow * 40 + seg * 8) * 2;
            size_t gA = (size_t)grc * DIM + k0 + seg * 8;
            cp16z(base + 0 * TILE_BYTES + soff, AH + gA, asz);
            cp16z(base + 1 * TILE_BYTES + soff, AL + gA, asz);
            size_t gB = (size_t)brow * DIM + k0 + seg * 8;
            cp16(base + 2 * TILE_BYTES + soff, WH + gB);
            cp16(base + 3 * TILE_BYTES + soff, WL + gB);
        }
        CP_COMMIT();
    };

    stage_load(0, 0);

    for (int kt = 0; kt < 16; ++kt) {
        int s = kt & 1;
        if (kt + 1 < 16) {
            stage_load(kt + 1, s ^ 1);
            asm volatile("cp.async.wait_group 1;");
        } else {
            asm volatile("cp.async.wait_group 0;");
        }
        __syncthreads();

        uint32_t uAh = sb + s * STAGE_BYTES;
        uint32_t uAl = uAh + TILE_BYTES;
        uint32_t uBh = uAh + 2 * TILE_BYTES;
        uint32_t uBl = uAh + 3 * TILE_BYTES;

        #pragma unroll
        for (int ks = 0; ks < 2; ++ks) {
            int kcol = ks * 16;
            uint32_t ah[2][4], al[2][4];
            #pragma unroll
            for (int mt = 0; mt < 2; ++mt) {
                int row = wm * 32 + mt * 16 + a_r;
                uint32_t off = (uint32_t)(row * 40 + kcol + a_c) * 2;
                LDMX4(ah[mt][0], ah[mt][1], ah[mt][2], ah[mt][3], uAh + off);
                LDMX4(al[mt][0], al[mt][1], al[mt][2], al[mt][3], uAl + off);
            }
            uint32_t bb[8][2];
            #pragma unroll
            for (int g = 0; g < 4; ++g) {
                int row = wn * 64 + g * 16 + b_r;
                uint32_t off = (uint32_t)(row * 40 + kcol + b_c) * 2;
                LDMX4(bb[2 * g][0], bb[2 * g][1], bb[2 * g + 1][0], bb[2 * g + 1][1], uBh + off);
            }
            #pragma unroll
            for (int mt = 0; mt < 2; ++mt)
                #pragma unroll
                for (int nt = 0; nt < 8; ++nt)
                    MMA16816(acc[mt][nt], ah[mt][0], ah[mt][1], ah[mt][2], ah[mt][3], bb[nt][0], bb[nt][1]);
            #pragma unroll
            for (int mt = 0; mt < 2; ++mt)
                #pragma unroll
                for (int nt = 0; nt < 8; ++nt)
                    MMA16816(acc[mt][nt], al[mt][0], al[mt][1], al[mt][2], al[mt][3], bb[nt][0], bb[nt][1]);
            #pragma unroll
            for (int g = 0; g < 4; ++g) {
                int row = wn * 64 + g * 16 + b_r;
                uint32_t off = (uint32_t)(row * 40 + kcol + b_c) * 2;
                LDMX4(bb[2 * g][0], bb[2 * g][1], bb[2 * g + 1][0], bb[2 * g + 1][1], uBl + off);
            }
            #pragma unroll
            for (int mt = 0; mt < 2; ++mt)
                #pragma unroll
                for (int nt = 0; nt < 8; ++nt)
                    MMA16816(acc[mt][nt], ah[mt][0], ah[mt][1], ah[mt][2], ah[mt][3], bb[nt][0], bb[nt][1]);
        }
        __syncthreads();
    }

    #pragma unroll
    for (int nt = 0; nt < 8; ++nt) {
        int c = bn + wn * 64 + nt * 8 + (lane & 3) * 2;
        float bb0 = bias[c], bb1 = bias[c + 1];
        #pragma unroll
        for (int mt = 0; mt < 2; ++mt) {
            int r0 = bm + wm * 32 + mt * 16 + (lane >> 2);
            #pragma unroll
            for (int half = 0; half < 2; ++half) {
                int r = r0 + half * 8;
                if (r >= M) continue;
                float v0 = acc[mt][nt][2 * half]     + bb0;
                float v1 = acc[mt][nt][2 * half + 1] + bb1;
                v0 = v0 >= 0.f ? v0 : NEG * v0;
                v1 = v1 >= 0.f ? v1 : NEG * v1;
                if (MODE == 0) {
                    __nv_bfloat162 hh = pk2(v0, v1);
                    float l0 = v0 - __bfloat162float(hh.x);
                    float l1 = v1 - __bfloat162float(hh.y);
                    *(__nv_bfloat162*)(g_hi2 + (size_t)r * DIM + c) = hh;
                    *(__nv_bfloat162*)(g_lo2 + (size_t)r * DIM + c) = pk2(l0, l1);
                } else {
                    *(float2*)(g_bufA + (size_t)r * DIM + c) = make_float2(v0, v1);
                }
            }
        }
    }
}

// ---------------- row stats: warp per row (read-only pass) ----------------
__global__ void k_rowstats() {
    int w = blockIdx.x * 8 + (threadIdx.x >> 5);
    if (w >= NNODES) return;
    int lane = threadIdx.x & 31;
    const float4* row = (const float4*)(g_bufA + (size_t)w * DIM);
    float s = 0.f, q = 0.f;
    #pragma unroll
    for (int k = 0; k < 4; ++k) {
        float4 v = __ldg(row + k * 32 + lane);
        s += v.x + v.y + v.z + v.w;
        q += v.x * v.x + v.y * v.y + v.z * v.z + v.w * v.w;
    }
    #pragma unroll
    for (int o = 16; o; o >>= 1) {
        s += __shfl_down_sync(0xffffffffu, s, o);
        q += __shfl_down_sync(0xffffffffu, q, o);
    }
    if (lane == 0) {
        float mean = s * (1.0f / DIM);
        float var  = q * (1.0f / DIM) - mean * mean;
        g_rowmean[w] = mean;
        g_rowinv[w]  = rsqrtf(var + EPSF);
    }
}

// ---------------- col partial stats with on-the-fly NodeNorm (no atomics) ----------
__global__ void k_colstats() {
    int c  = blockIdx.x * 128 + threadIdx.x;    // blockIdx.x in [0,4)
    int rb = blockIdx.y;                        // 0..63
    const int ROWS_PER = 782;
    int r0 = rb * ROWS_PER;
    int r1 = r0 + ROWS_PER; if (r1 > NNODES) r1 = NNODES;
    float s = 0.f, q = 0.f;
    for (int r = r0; r < r1; ++r) {
        float zn = (g_bufA[(size_t)r * DIM + c] - g_rowmean[r]) * g_rowinv[r];
        s += zn; q += zn * zn;
    }
    g_colps[rb * DIM + c] = s;
    g_colpq[rb * DIM + c] = q;
}
__global__ void k_bnfinal(const float* __restrict__ gamma, const float* __restrict__ beta) {
    int c = threadIdx.x;  // 512
    float s = 0.f, q = 0.f;
    for (int i = 0; i < 64; ++i) {
        s += g_colps[i * DIM + c];
        q += g_colpq[i * DIM + c];
    }
    float mean = s * (1.0f / NNODES);
    float var  = q * (1.0f / NNODES) - mean * mean;
    float inv  = rsqrtf(var + EPSF);
    float sc   = gamma[c] * inv;
    g_scale[c] = sc;
    g_shift[c] = beta[c] - mean * sc;
}

// ---------------- apply NodeNorm + BN -> x_local slice ----------------
__global__ void k_apply(float* __restrict__ xlocal, int layer) {
    int idx = blockIdx.x * blockDim.x + threadIdx.x;
    if (idx >= NNODES * (DIM / 4)) return;
    int n  = idx / (DIM / 4);
    int c4 = idx % (DIM / 4);
    float mean = g_rowmean[n];
    float inv  = g_rowinv[n];
    float4 v = ((const float4*)g_bufA)[idx];
    int c = c4 * 4;
    v.x = (v.x - mean) * inv * g_scale[c + 0] + g_shift[c + 0];
    v.y = (v.y - mean) * inv * g_scale[c + 1] + g_shift[c + 1];
    v.z = (v.z - mean) * inv * g_scale[c + 2] + g_shift[c + 2];
    v.w = (v.w - mean) * inv * g_scale[c + 3] + g_shift[c + 3];
    ((float4*)(xlocal + (size_t)n * OUTD + (size_t)layer * DIM))[c4] = v;
}
__global__ void k_pool(const float* __restrict__ xlocal, float* __restrict__ xglobal) {
    int g = blockIdx.x;
    int c = blockIdx.y * 128 + threadIdx.x;
    int r0 = g_gstart[g], r1 = g_gstart[g + 1];
    float s = 0.f;
    for (int r = r0; r < r1; ++r) s += xlocal[(size_t)r * OUTD + c];
    xglobal[(size_t)g * OUTD + c] = s;
}

// ---------------- driver ----------------
extern "C" void kernel_launch(void* const* d_in, const int* in_sizes, int n_in,
                              void* d_out, int out_size) {
    const float* x     = (const float*)d_in[0];
    const int*   ei    = (const int*)d_in[1];
    const int*   batch = (const int*)d_in[2];
    const float* W1    = (const float*)d_in[3];
    const float* b1    = (const float*)d_in[4];
    const float* W2    = (const float*)d_in[5];
    const float* b2    = (const float*)d_in[6];
    const float* gamma = (const float*)d_in[7];
    const float* beta  = (const float*)d_in[8];

    float* out     = (float*)d_out;
    float* xglobal = out;
    float* xlocal  = out + (size_t)NGRAPHS * OUTD;

    cudaFuncSetAttribute(k_mma<0>, cudaFuncAttributeMaxDynamicSharedMemorySize, SMEM_TOTAL);
    cudaFuncSetAttribute(k_mma<1>, cudaFuncAttributeMaxDynamicSharedMemorySize, SMEM_TOTAL);

    k_wconv_all<<<dim3(16, 16, 8), dim3(32, 32)>>>(W1, W2);   // also zeroes g_cur
    k_count<<<(NEDGES + 255) / 256, 256>>>(ei);
    k_scan<<<1, 1024>>>();
    k_fill<<<(NEDGES + 255) / 256, 256>>>(ei);

    dim3 mma_grid(4, (NNODES + 127) / 128);

    for (int l = 0; l < NLAYERS; ++l) {
        const float* h = (l == 0) ? x : (xlocal + (size_t)(l - 1) * DIM);
        int ldh = (l == 0) ? DIM : OUTD;
        k_aggregate<<<NNODES, 128>>>(h, ldh);
        k_mma<0><<<mma_grid, 256, SMEM_TOTAL>>>(l, b1 + (size_t)l * DIM, NNODES);
        k_mma<1><<<mma_grid, 256, SMEM_TOTAL>>>(l, b2 + (size_t)l * DIM, NNODES);
        k_rowstats<<<(NNODES + 7) / 8, 256>>>();
        k_colstats<<<dim3(4, 64), 128>>>();
        k_bnfinal<<<1, 512>>>(gamma + (size_t)l * DIM, beta + (size_t)l * DIM);
        k_apply<<<(NNODES * (DIM / 4) + 255) / 256, 256>>>(xlocal, l);
    }

    k_gstart<<<2, 256>>>(batch);
    k_pool<<<dim3(NGRAPHS, 16), 128>>>(xlocal, xglobal);
}

// round 14
// speedup vs baseline: 1.0932x; 1.0932x over previous
#include <cuda_runtime.h>
#include <cuda_bf16.h>
#include <cstdint>

#define NNODES 50000
#define NEDGES 400000
#define DIM 512
#define NLAYERS 4
#define NGRAPHS 500
#define OUTD 2048
#define EPSF 1e-5f
#define NEG 0.01f

// ---------------- scratch ----------------
__device__ float g_bufA[(size_t)NNODES * DIM];
__device__ __nv_bfloat16 g_hi[(size_t)NNODES * DIM];    // GEMM1 input (from aggregate)
__device__ __nv_bfloat16 g_lo[(size_t)NNODES * DIM];
__device__ __nv_bfloat16 g_hi2[(size_t)NNODES * DIM];   // GEMM1 output / GEMM2 input
__device__ __nv_bfloat16 g_lo2[(size_t)NNODES * DIM];
__device__ __nv_bfloat16 g_wt1h[NLAYERS * DIM * DIM], g_wt1l[NLAYERS * DIM * DIM];
__device__ __nv_bfloat16 g_wt2h[NLAYERS * DIM * DIM], g_wt2l[NLAYERS * DIM * DIM];
__device__ int   g_off[NNODES + 1];
__device__ int   g_cur[NNODES];
__device__ int   g_esrc[NEDGES];
__device__ float g_colsum[DIM];
__device__ float g_colsq[DIM];
__device__ float g_scale[DIM];
__device__ float g_shift[DIM];
__device__ int   g_gstart[NGRAPHS + 1];

__device__ __forceinline__ uint32_t smem_u32(const void* p) {
    uint32_t a;
    asm("{ .reg .u64 t; cvta.to.shared.u64 t, %1; cvt.u32.u64 %0, t; }" : "=r"(a) : "l"(p));
    return a;
}

#define LDMX4(r0, r1, r2, r3, addr) \
    asm volatile("ldmatrix.sync.aligned.m8n8.x4.shared.b16 {%0,%1,%2,%3}, [%4];" \
        : "=r"(r0), "=r"(r1), "=r"(r2), "=r"(r3) : "r"(addr))

#define MMA16816(d, a0, a1, a2, a3, b0, b1) \
    asm volatile("mma.sync.aligned.m16n8k16.row.col.f32.bf16.bf16.f32 " \
        "{%0,%1,%2,%3}, {%4,%5,%6,%7}, {%8,%9}, {%0,%1,%2,%3};" \
        : "+f"((d)[0]), "+f"((d)[1]), "+f"((d)[2]), "+f"((d)[3]) \
        : "r"(a0), "r"(a1), "r"(a2), "r"(a3), "r"(b0), "r"(b1))

__device__ __forceinline__ void cp16z(uint32_t dst, const void* src, int srcsize) {
    asm volatile("cp.async.cg.shared.global [%0], [%1], 16, %2;" :: "r"(dst), "l"(src), "r"(srcsize));
}
__device__ __forceinline__ void cp16(uint32_t dst, const void* src) {
    asm volatile("cp.async.cg.shared.global [%0], [%1], 16;" :: "r"(dst), "l"(src));
}
#define CP_COMMIT() asm volatile("cp.async.commit_group;")

__device__ __forceinline__ __nv_bfloat162 pk2(float a, float b) {
    __nv_bfloat162 r; r.x = __float2bfloat16(a); r.y = __float2bfloat16(b); return r;
}

// ---------------- weights conversion + g_cur zeroing (launch #1) ----------------
__global__ void k_wconv_all(const float* __restrict__ W1, const float* __restrict__ W2) {
    int gb = (blockIdx.z * gridDim.y + blockIdx.y) * gridDim.x + blockIdx.x;
    int gidx = gb * 1024 + threadIdx.y * 32 + threadIdx.x;
    if (gidx < NNODES) g_cur[gidx] = 0;

    __shared__ float tile[32][33];
    int zc = blockIdx.z;
    int l = zc >> 1, which = zc & 1;
    const float* W = ((which == 0) ? W1 : W2) + (size_t)l * DIM * DIM;
    int k0 = blockIdx.y * 32, n0 = blockIdx.x * 32;
    int tx = threadIdx.x, ty = threadIdx.y;
    tile[ty][tx] = W[(size_t)(k0 + ty) * DIM + n0 + tx];
    __syncthreads();
    float v = tile[tx][ty];
    __nv_bfloat16 h = __float2bfloat16(v);
    float lo = v - __bfloat162float(h);
    size_t idx = (size_t)l * DIM * DIM + (size_t)(n0 + ty) * DIM + k0 + tx;
    if (which == 0) { g_wt1h[idx] = h; g_wt1l[idx] = __float2bfloat16(lo); }
    else            { g_wt2h[idx] = h; g_wt2l[idx] = __float2bfloat16(lo); }
}

// ---------------- CSR build ----------------
__global__ void k_count(const int* __restrict__ ei) {
    int e = blockIdx.x * blockDim.x + threadIdx.x;
    if (e < NEDGES) atomicAdd(&g_cur[ei[NEDGES + e]], 1);
}
__global__ void k_scan() {
    __shared__ int wsum[32];
    __shared__ int carry_s;
    int tid = threadIdx.x, lane = tid & 31, wid = tid >> 5;
    if (tid == 0) carry_s = 0;
    __syncthreads();
    for (int base = 0; base < NNODES; base += 1024) {
        int i = base + tid;
        int orig = (i < NNODES) ? g_cur[i] : 0;
        int v = orig;
        #pragma unroll
        for (int o = 1; o < 32; o <<= 1) {
            int t = __shfl_up_sync(0xffffffffu, v, o);
            if (lane >= o) v += t;
        }
        if (lane == 31) wsum[wid] = v;
        __syncthreads();
        if (wid == 0) {
            int s = wsum[lane];
            #pragma unroll
            for (int o = 1; o < 32; o <<= 1) {
                int t = __shfl_up_sync(0xffffffffu, s, o);
                if (lane >= o) s += t;
            }
            wsum[lane] = s;
        }
        __syncthreads();
        int prev = (wid > 0) ? wsum[wid - 1] : 0;
        int incl = carry_s + prev + v;
        int excl = incl - orig;
        if (i < NNODES) { g_off[i] = excl; g_cur[i] = excl; }
        __syncthreads();
        if (tid == 1023) carry_s = incl;
        __syncthreads();
    }
    if (threadIdx.x == 0) g_off[NNODES] = carry_s;
}
__global__ void k_fill(const int* __restrict__ ei) {
    int e = blockIdx.x * blockDim.x + threadIdx.x;
    if (e < NEDGES) {
        int p = atomicAdd(&g_cur[ei[NEDGES + e]], 1);
        g_esrc[p] = ei[e];
    }
}
__global__ void k_gstart(const int* __restrict__ batch) {
    int g = blockIdx.x * blockDim.x + threadIdx.x;
    if (g > NGRAPHS) return;
    int lo = 0, hi = NNODES;
    while (lo < hi) {
        int mid = (lo + hi) >> 1;
        if (batch[mid] < g) lo = mid + 1; else hi = mid;
    }
    g_gstart[g] = lo;
}

// ---------------- aggregation -> split bf16 into g_hi/g_lo ----------------
__global__ void k_aggregate(const float* __restrict__ h, int ldh) {
    int n = blockIdx.x;
    int t = threadIdx.x;   // 128 threads * 4 cols
    float4 acc = __ldg((const float4*)(h + (size_t)n * ldh) + t);
    int e0 = g_off[n], e1 = g_off[n + 1];
    for (int e = e0; e < e1; ++e) {
        int s = g_esrc[e];
        float4 v = __ldg((const float4*)(h + (size_t)s * ldh) + t);
        acc.x += v.x; acc.y += v.y; acc.z += v.z; acc.w += v.w;
    }
    __nv_bfloat162 h01 = pk2(acc.x, acc.y), h23 = pk2(acc.z, acc.w);
    float lx = acc.x - __bfloat162float(h01.x);
    float ly = acc.y - __bfloat162float(h01.y);
    float lz = acc.z - __bfloat162float(h23.x);
    float lw = acc.w - __bfloat162float(h23.y);
    __nv_bfloat162* hp = (__nv_bfloat162*)(g_hi + (size_t)n * DIM);
    __nv_bfloat162* lp = (__nv_bfloat162*)(g_lo + (size_t)n * DIM);
    hp[2 * t] = h01; hp[2 * t + 1] = h23;
    lp[2 * t] = pk2(lx, ly); lp[2 * t + 1] = pk2(lz, lw);
}

// ---------------- mma.sync GEMM (byte-identical to round-12 passing version) ----------
#define TILE_BYTES 10240          // 128*40*2
#define STAGE_BYTES 40960
#define SMEM_TOTAL 81920

template <int MODE>
__global__ void __launch_bounds__(256, 2) k_mma(int layer, const float* __restrict__ bias, int M) {
    extern __shared__ char smem[];
    uint32_t sb = smem_u32(smem);

    size_t wo = (size_t)layer * DIM * DIM;
    const __nv_bfloat16* AH = (MODE == 0) ? g_hi : g_hi2;
    const __nv_bfloat16* AL = (MODE == 0) ? g_lo : g_lo2;
    const __nv_bfloat16* WH = ((MODE == 0) ? g_wt1h : g_wt2h) + wo;
    const __nv_bfloat16* WL = ((MODE == 0) ? g_wt1l : g_wt2l) + wo;

    int tid  = threadIdx.x;
    int lane = tid & 31;
    int wid  = tid >> 5;
    int wm   = wid & 3;
    int wn   = wid >> 2;
    int bm   = blockIdx.y * 128;
    int bn   = blockIdx.x * 128;

    float acc[2][8][4];
    #pragma unroll
    for (int i = 0; i < 2; ++i)
        #pragma unroll
        for (int j = 0; j < 8; ++j)
            #pragma unroll
            for (int q = 0; q < 4; ++q) acc[i][j][q] = 0.f;

    int lrow = tid >> 1;
    int lseg = (tid & 1) * 2;

    int a_r = (lane & 7) + ((lane >> 3) & 1) * 8;
    int a_c = (lane >> 4) * 8;
    int b_r = (lane & 7) + (lane >> 4) * 8;
    int b_c = ((lane >> 3) & 1) * 8;

    int gr = bm + lrow;
    int asz = (gr < M) ? 16 : 0;
    int grc = (gr < M) ? gr : (M - 1);
    int brow = bn + lrow;

    auto stage_load = [&](int kt, int s) {
        int k0 = kt * 32;
        uint32_t base = sb + s * STAGE_BYTES;
        #pragma unroll
        for (int j = 0; j < 2; ++j) {
            int seg = lseg + j;
            uint32_t soff = (uint32_t)(lrow * 40 + seg * 8) * 2;
            size_t gA = (size_t)grc * DIM + k0 + seg * 8;
            cp16z(base + 0 * TILE_BYTES + soff, AH + gA, asz);
            cp16z(base + 1 * TILE_BYTES + soff, AL + gA, asz);
            size_t gB = (size_t)brow * DIM + k0 + seg * 8;
            cp16(base + 2 * TILE_BYTES + soff, WH + gB);
            cp16(base + 3 * TILE_BYTES + soff, WL + gB);
        }
        CP_COMMIT();
    };

    stage_load(0, 0);

    for (int kt = 0; kt < 16; ++kt) {
        int s = kt & 1;
        if (kt + 1 < 16) {
            stage_load(kt + 1, s ^ 1);
            asm volatile("cp.async.wait_group 1;");
        } else {
            asm volatile("cp.async.wait_group 0;");
        }
        __syncthreads();

        uint32_t uAh = sb + s * STAGE_BYTES;
        uint32_t uAl = uAh + TILE_BYTES;
        uint32_t uBh = uAh + 2 * TILE_BYTES;
        uint32_t uBl = uAh + 3 * TILE_BYTES;

        #pragma unroll
        for (int ks = 0; ks < 2; ++ks) {
            int kcol = ks * 16;
            uint32_t ah[2][4], al[2][4];
            #pragma unroll
            for (int mt = 0; mt < 2; ++mt) {
                int row = wm * 32 + mt * 16 + a_r;
                uint32_t off = (uint32_t)(row * 40 + kcol + a_c) * 2;
                LDMX4(ah[mt][0], ah[mt][1], ah[mt][2], ah[mt][3], uAh + off);
                LDMX4(al[mt][0], al[mt][1], al[mt][2], al[mt][3], uAl + off);
            }
            uint32_t bb[8][2];
            #pragma unroll
            for (int g = 0; g < 4; ++g) {
                int row = wn * 64 + g * 16 + b_r;
                uint32_t off = (uint32_t)(row * 40 + kcol + b_c) * 2;
                LDMX4(bb[2 * g][0], bb[2 * g][1], bb[2 * g + 1][0], bb[2 * g + 1][1], uBh + off);
            }
            #pragma unroll
            for (int mt = 0; mt < 2; ++mt)
                #pragma unroll
                for (int nt = 0; nt < 8; ++nt)
                    MMA16816(acc[mt][nt], ah[mt][0], ah[mt][1], ah[mt][2], ah[mt][3], bb[nt][0], bb[nt][1]);
            #pragma unroll
            for (int mt = 0; mt < 2; ++mt)
                #pragma unroll
                for (int nt = 0; nt < 8; ++nt)
                    MMA16816(acc[mt][nt], al[mt][0], al[mt][1], al[mt][2], al[mt][3], bb[nt][0], bb[nt][1]);
            #pragma unroll
            for (int g = 0; g < 4; ++g) {
                int row = wn * 64 + g * 16 + b_r;
                uint32_t off = (uint32_t)(row * 40 + kcol + b_c) * 2;
                LDMX4(bb[2 * g][0], bb[2 * g][1], bb[2 * g + 1][0], bb[2 * g + 1][1], uBl + off);
            }
            #pragma unroll
            for (int mt = 0; mt < 2; ++mt)
                #pragma unroll
                for (int nt = 0; nt < 8; ++nt)
                    MMA16816(acc[mt][nt], ah[mt][0], ah[mt][1], ah[mt][2], ah[mt][3], bb[nt][0], bb[nt][1]);
        }
        __syncthreads();
    }

    #pragma unroll
    for (int nt = 0; nt < 8; ++nt) {
        int c = bn + wn * 64 + nt * 8 + (lane & 3) * 2;
        float bb0 = bias[c], bb1 = bias[c + 1];
        #pragma unroll
        for (int mt = 0; mt < 2; ++mt) {
            int r0 = bm + wm * 32 + mt * 16 + (lane >> 2);
            #pragma unroll
            for (int half = 0; half < 2; ++half) {
                int r = r0 + half * 8;
                if (r >= M) continue;
                float v0 = acc[mt][nt][2 * half]     + bb0;
                float v1 = acc[mt][nt][2 * half + 1] + bb1;
                v0 = v0 >= 0.f ? v0 : NEG * v0;
                v1 = v1 >= 0.f ? v1 : NEG * v1;
                if (MODE == 0) {
                    __nv_bfloat162 hh = pk2(v0, v1);
                    float l0 = v0 - __bfloat162float(hh.x);
                    float l1 = v1 - __bfloat162float(hh.y);
                    *(__nv_bfloat162*)(g_hi2 + (size_t)r * DIM + c) = hh;
                    *(__nv_bfloat162*)(g_lo2 + (size_t)r * DIM + c) = pk2(l0, l1);
                } else {
                    *(float2*)(g_bufA + (size_t)r * DIM + c) = make_float2(v0, v1);
                }
            }
        }
    }
}

// ---------------- NodeNorm (in place on g_bufA) + fold col-stat zeroing ----------------
__global__ void k_nodenorm() {
    int n = blockIdx.x;
    int t = threadIdx.x;   // 128
    // blocks 0-3 also zero BN accumulators (ordering guaranteed by kernel boundary)
    if (n < 4) {
        g_colsum[n * 128 + t] = 0.f;
        g_colsq[n * 128 + t]  = 0.f;
    }
    float4* row = (float4*)(g_bufA + (size_t)n * DIM);
    float4 v = row[t];
    float s  = v.x + v.y + v.z + v.w;
    float sq = v.x * v.x + v.y * v.y + v.z * v.z + v.w * v.w;
    #pragma unroll
    for (int o = 16; o; o >>= 1) {
        s  += __shfl_down_sync(0xffffffffu, s, o);
        sq += __shfl_down_sync(0xffffffffu, sq, o);
    }
    __shared__ float ssum[4], ssq[4];
    int lane = t & 31, wid = t >> 5;
    if (lane == 0) { ssum[wid] = s; ssq[wid] = sq; }
    __syncthreads();
    float S = ssum[0] + ssum[1] + ssum[2] + ssum[3];
    float Q = ssq[0] + ssq[1] + ssq[2] + ssq[3];
    float mean = S * (1.0f / DIM);
    float var  = Q * (1.0f / DIM) - mean * mean;
    float inv  = rsqrtf(var + EPSF);
    v.x = (v.x - mean) * inv;
    v.y = (v.y - mean) * inv;
    v.z = (v.z - mean) * inv;
    v.w = (v.w - mean) * inv;
    row[t] = v;
}

// ---------------- BatchNorm ----------------
__global__ void k_colstats() {
    int c = blockIdx.x * 128 + threadIdx.x;
    const int ROWS_PER = 782;
    int r0 = blockIdx.y * ROWS_PER;
    int r1 = r0 + ROWS_PER; if (r1 > NNODES) r1 = NNODES;
    float s = 0.f, q = 0.f;
    for (int r = r0; r < r1; ++r) {
        float v = g_bufA[(size_t)r * DIM + c];
        s += v; q += v * v;
    }
    atomicAdd(&g_colsum[c], s);
    atomicAdd(&g_colsq[c], q);
}
__global__ void k_bnfinal(const float* __restrict__ gamma, const float* __restrict__ beta) {
    int c = threadIdx.x;
    float mean = g_colsum[c] * (1.0f / NNODES);
    float var  = g_colsq[c] * (1.0f / NNODES) - mean * mean;
    float inv  = rsqrtf(var + EPSF);
    float sc   = gamma[c] * inv;
    g_scale[c] = sc;
    g_shift[c] = beta[c] - mean * sc;
}
__global__ void k_apply(float* __restrict__ xlocal, int layer) {
    int idx = blockIdx.x * blockDim.x + threadIdx.x;
    if (idx >= NNODES * (DIM / 4)) return;
    int n  = idx / (DIM / 4);
    int c4 = idx % (DIM / 4);
    float4 v = ((const float4*)g_bufA)[idx];
    int c = c4 * 4;
    v.x = v.x * g_scale[c + 0] + g_shift[c + 0];
    v.y = v.y * g_scale[c + 1] + g_shift[c + 1];
    v.z = v.z * g_scale[c + 2] + g_shift[c + 2];
    v.w = v.w * g_scale[c + 3] + g_shift[c + 3];
    ((float4*)(xlocal + (size_t)n * OUTD + (size_t)layer * DIM))[c4] = v;
}

// ---------------- global_add_pool: float4 + 2-row unroll ----------------
__global__ void k_pool(const float* __restrict__ xlocal, float* __restrict__ xglobal) {
    int g  = blockIdx.x;
    int c4 = blockIdx.y * 128 + threadIdx.x;   // blockIdx.y in [0,4): 4*128 float4 = 2048 floats
    int r0 = g_gstart[g], r1 = g_gstart[g + 1];
    float4 s0 = make_float4(0.f, 0.f, 0.f, 0.f);
    float4 s1 = make_float4(0.f, 0.f, 0.f, 0.f);
    int r = r0;
    for (; r + 1 < r1; r += 2) {
        float4 a = __ldg((const float4*)(xlocal + (size_t)r * OUTD) + c4);
        float4 b = __ldg((const float4*)(xlocal + (size_t)(r + 1) * OUTD) + c4);
        s0.x += a.x; s0.y += a.y; s0.z += a.z; s0.w += a.w;
        s1.x += b.x; s1.y += b.y; s1.z += b.z; s1.w += b.w;
    }
    if (r < r1) {
        float4 a = __ldg((const float4*)(xlocal + (size_t)r * OUTD) + c4);
        s0.x += a.x; s0.y += a.y; s0.z += a.z; s0.w += a.w;
    }
    s0.x += s1.x; s0.y += s1.y; s0.z += s1.z; s0.w += s1.w;
    ((float4*)(xglobal + (size_t)g * OUTD))[c4] = s0;
}

// ---------------- driver ----------------
extern "C" void kernel_launch(void* const* d_in, const int* in_sizes, int n_in,
                              void* d_out, int out_size) {
    const float* x     = (const float*)d_in[0];
    const int*   ei    = (const int*)d_in[1];
    const int*   batch = (const int*)d_in[2];
    const float* W1    = (const float*)d_in[3];
    const float* b1    = (const float*)d_in[4];
    const float* W2    = (const float*)d_in[5];
    const float* b2    = (const float*)d_in[6];
    const float* gamma = (const float*)d_in[7];
    const float* beta  = (const float*)d_in[8];

    float* out     = (float*)d_out;
    float* xglobal = out;
    float* xlocal  = out + (size_t)NGRAPHS * OUTD;

    cudaFuncSetAttribute(k_mma<0>, cudaFuncAttributeMaxDynamicSharedMemorySize, SMEM_TOTAL);
    cudaFuncSetAttribute(k_mma<1>, cudaFuncAttributeMaxDynamicSharedMemorySize, SMEM_TOTAL);

    k_wconv_all<<<dim3(16, 16, 8), dim3(32, 32)>>>(W1, W2);   // also zeroes g_cur
    k_count<<<(NEDGES + 255) / 256, 256>>>(ei);
    k_scan<<<1, 1024>>>();
    k_fill<<<(NEDGES + 255) / 256, 256>>>(ei);

    dim3 mma_grid(4, (NNODES + 127) / 128);

    for (int l = 0; l < NLAYERS; ++l) {
        const float* h = (l == 0) ? x : (xlocal + (size_t)(l - 1) * DIM);
        int ldh = (l == 0) ? DIM : OUTD;
        k_aggregate<<<NNODES, 128>>>(h, ldh);
        k_mma<0><<<mma_grid, 256, SMEM_TOTAL>>>(l, b1 + (size_t)l * DIM, NNODES);
        k_mma<1><<<mma_grid, 256, SMEM_TOTAL>>>(l, b2 + (size_t)l * DIM, NNODES);
        k_nodenorm<<<NNODES, 128>>>();          // also zeroes col accumulators
        k_colstats<<<dim3(4, 64), 128>>>();
        k_bnfinal<<<1, 512>>>(gamma + (size_t)l * DIM, beta + (size_t)l * DIM);
        k_apply<<<(NNODES * (DIM / 4) + 255) / 256, 256>>>(xlocal, l);
    }

    k_gstart<<<2, 256>>>(batch);
    k_pool<<<dim3(NGRAPHS, 4), 128>>>(xlocal, xglobal);
}

// round 15
// speedup vs baseline: 1.0972x; 1.0036x over previous
#include <cuda_runtime.h>
#include <cuda_bf16.h>
#include <cstdint>

#define NNODES 50000
#define NEDGES 400000
#define DIM 512
#define NLAYERS 4
#define NGRAPHS 500
#define OUTD 2048
#define EPSF 1e-5f
#define NEG 0.01f

// ---------------- scratch ----------------
__device__ float g_bufA[(size_t)NNODES * DIM];
__device__ __nv_bfloat16 g_hi[(size_t)NNODES * DIM];    // GEMM1 input (from aggregate)
__device__ __nv_bfloat16 g_lo[(size_t)NNODES * DIM];
__device__ __nv_bfloat16 g_hi2[(size_t)NNODES * DIM];   // GEMM1 output / GEMM2 input
__device__ __nv_bfloat16 g_lo2[(size_t)NNODES * DIM];
__device__ __nv_bfloat16 g_wt1h[NLAYERS * DIM * DIM], g_wt1l[NLAYERS * DIM * DIM];
__device__ __nv_bfloat16 g_wt2h[NLAYERS * DIM * DIM], g_wt2l[NLAYERS * DIM * DIM];
__device__ int   g_off[NNODES + 1];
__device__ int   g_cur[NNODES];
__device__ int   g_esrc[NEDGES];
__device__ float g_colsum[DIM];
__device__ float g_colsq[DIM];
__device__ float g_scale[DIM];
__device__ float g_shift[DIM];

__device__ __forceinline__ uint32_t smem_u32(const void* p) {
    uint32_t a;
    asm("{ .reg .u64 t; cvta.to.shared.u64 t, %1; cvt.u32.u64 %0, t; }" : "=r"(a) : "l"(p));
    return a;
}

#define LDMX4(r0, r1, r2, r3, addr) \
    asm volatile("ldmatrix.sync.aligned.m8n8.x4.shared.b16 {%0,%1,%2,%3}, [%4];" \
        : "=r"(r0), "=r"(r1), "=r"(r2), "=r"(r3) : "r"(addr))

#define MMA16816(d, a0, a1, a2, a3, b0, b1) \
    asm volatile("mma.sync.aligned.m16n8k16.row.col.f32.bf16.bf16.f32 " \
        "{%0,%1,%2,%3}, {%4,%5,%6,%7}, {%8,%9}, {%0,%1,%2,%3};" \
        : "+f"((d)[0]), "+f"((d)[1]), "+f"((d)[2]), "+f"((d)[3]) \
        : "r"(a0), "r"(a1), "r"(a2), "r"(a3), "r"(b0), "r"(b1))

__device__ __forceinline__ void cp16z(uint32_t dst, const void* src, int srcsize) {
    asm volatile("cp.async.cg.shared.global [%0], [%1], 16, %2;" :: "r"(dst), "l"(src), "r"(srcsize));
}
__device__ __forceinline__ void cp16(uint32_t dst, const void* src) {
    asm volatile("cp.async.cg.shared.global [%0], [%1], 16;" :: "r"(dst), "l"(src));
}
#define CP_COMMIT() asm volatile("cp.async.commit_group;")

__device__ __forceinline__ __nv_bfloat162 pk2(float a, float b) {
    __nv_bfloat162 r; r.x = __float2bfloat16(a); r.y = __float2bfloat16(b); return r;
}

// ---------------- weights conversion + g_cur zeroing (launch #1) ----------------
__global__ void k_wconv_all(const float* __restrict__ W1, const float* __restrict__ W2) {
    int gb = (blockIdx.z * gridDim.y + blockIdx.y) * gridDim.x + blockIdx.x;
    int gidx = gb * 1024 + threadIdx.y * 32 + threadIdx.x;
    if (gidx < NNODES) g_cur[gidx] = 0;

    __shared__ float tile[32][33];
    int zc = blockIdx.z;
    int l = zc >> 1, which = zc & 1;
    const float* W = ((which == 0) ? W1 : W2) + (size_t)l * DIM * DIM;
    int k0 = blockIdx.y * 32, n0 = blockIdx.x * 32;
    int tx = threadIdx.x, ty = threadIdx.y;
    tile[ty][tx] = W[(size_t)(k0 + ty) * DIM + n0 + tx];
    __syncthreads();
    float v = tile[tx][ty];
    __nv_bfloat16 h = __float2bfloat16(v);
    float lo = v - __bfloat162float(h);
    size_t idx = (size_t)l * DIM * DIM + (size_t)(n0 + ty) * DIM + k0 + tx;
    if (which == 0) { g_wt1h[idx] = h; g_wt1l[idx] = __float2bfloat16(lo); }
    else            { g_wt2h[idx] = h; g_wt2l[idx] = __float2bfloat16(lo); }
}

// ---------------- CSR build ----------------
__global__ void k_count(const int* __restrict__ ei) {
    int e = blockIdx.x * blockDim.x + threadIdx.x;
    if (e < NEDGES) atomicAdd(&g_cur[ei[NEDGES + e]], 1);
}
__global__ void k_scan() {
    __shared__ int wsum[32];
    __shared__ int carry_s;
    int tid = threadIdx.x, lane = tid & 31, wid = tid >> 5;
    if (tid == 0) carry_s = 0;
    __syncthreads();
    for (int base = 0; base < NNODES; base += 1024) {
        int i = base + tid;
        int orig = (i < NNODES) ? g_cur[i] : 0;
        int v = orig;
        #pragma unroll
        for (int o = 1; o < 32; o <<= 1) {
            int t = __shfl_up_sync(0xffffffffu, v, o);
            if (lane >= o) v += t;
        }
        if (lane == 31) wsum[wid] = v;
        __syncthreads();
        if (wid == 0) {
            int s = wsum[lane];
            #pragma unroll
            for (int o = 1; o < 32; o <<= 1) {
                int t = __shfl_up_sync(0xffffffffu, s, o);
                if (lane >= o) s += t;
            }
            wsum[lane] = s;
        }
        __syncthreads();
        int prev = (wid > 0) ? wsum[wid - 1] : 0;
        int incl = carry_s + prev + v;
        int excl = incl - orig;
        if (i < NNODES) { g_off[i] = excl; g_cur[i] = excl; }
        __syncthreads();
        if (tid == 1023) carry_s = incl;
        __syncthreads();
    }
    if (threadIdx.x == 0) g_off[NNODES] = carry_s;
}
__global__ void k_fill(const int* __restrict__ ei) {
    int e = blockIdx.x * blockDim.x + threadIdx.x;
    if (e < NEDGES) {
        int p = atomicAdd(&g_cur[ei[NEDGES + e]], 1);
        g_esrc[p] = ei[e];
    }
}

// ---------------- aggregation -> split bf16 into g_hi/g_lo ----------------
__global__ void k_aggregate(const float* __restrict__ h, int ldh) {
    int n = blockIdx.x;
    int t = threadIdx.x;   // 128 threads * 4 cols
    float4 acc = __ldg((const float4*)(h + (size_t)n * ldh) + t);
    int e0 = g_off[n], e1 = g_off[n + 1];
    for (int e = e0; e < e1; ++e) {
        int s = g_esrc[e];
        float4 v = __ldg((const float4*)(h + (size_t)s * ldh) + t);
        acc.x += v.x; acc.y += v.y; acc.z += v.z; acc.w += v.w;
    }
    __nv_bfloat162 h01 = pk2(acc.x, acc.y), h23 = pk2(acc.z, acc.w);
    float lx = acc.x - __bfloat162float(h01.x);
    float ly = acc.y - __bfloat162float(h01.y);
    float lz = acc.z - __bfloat162float(h23.x);
    float lw = acc.w - __bfloat162float(h23.y);
    __nv_bfloat162* hp = (__nv_bfloat162*)(g_hi + (size_t)n * DIM);
    __nv_bfloat162* lp = (__nv_bfloat162*)(g_lo + (size_t)n * DIM);
    hp[2 * t] = h01; hp[2 * t + 1] = h23;
    lp[2 * t] = pk2(lx, ly); lp[2 * t + 1] = pk2(lz, lw);
}

// ---------------- mma.sync GEMM (byte-identical to round-12 passing version) ----------
#define TILE_BYTES 10240          // 128*40*2
#define STAGE_BYTES 40960
#define SMEM_TOTAL 81920

template <int MODE>
__global__ void __launch_bounds__(256, 2) k_mma(int layer, const float* __restrict__ bias, int M) {
    extern __shared__ char smem[];
    uint32_t sb = smem_u32(smem);

    size_t wo = (size_t)layer * DIM * DIM;
    const __nv_bfloat16* AH = (MODE == 0) ? g_hi : g_hi2;
    const __nv_bfloat16* AL = (MODE == 0) ? g_lo : g_lo2;
    const __nv_bfloat16* WH = ((MODE == 0) ? g_wt1h : g_wt2h) + wo;
    const __nv_bfloat16* WL = ((MODE == 0) ? g_wt1l : g_wt2l) + wo;

    int tid  = threadIdx.x;
    int lane = tid & 31;
    int wid  = tid >> 5;
    int wm   = wid & 3;
    int wn   = wid >> 2;
    int bm   = blockIdx.y * 128;
    int bn   = blockIdx.x * 128;

    float acc[2][8][4];
    #pragma unroll
    for (int i = 0; i < 2; ++i)
        #pragma unroll
        for (int j = 0; j < 8; ++j)
            #pragma unroll
            for (int q = 0; q < 4; ++q) acc[i][j][q] = 0.f;

    int lrow = tid >> 1;
    int lseg = (tid & 1) * 2;

    int a_r = (lane & 7) + ((lane >> 3) & 1) * 8;
    int a_c = (lane >> 4) * 8;
    int b_r = (lane & 7) + (lane >> 4) * 8;
    int b_c = ((lane >> 3) & 1) * 8;

    int gr = bm + lrow;
    int asz = (gr < M) ? 16 : 0;
    int grc = (gr < M) ? gr : (M - 1);
    int brow = bn + lrow;

    auto stage_load = [&](int kt, int s) {
        int k0 = kt * 32;
        uint32_t base = sb + s * STAGE_BYTES;
        #pragma unroll
        for (int j = 0; j < 2; ++j) {
            int seg = lseg + j;
            uint32_t soff = (uint32_t)(lrow * 40 + seg * 8) * 2;
            size_t gA = (size_t)grc * DIM + k0 + seg * 8;
            cp16z(base + 0 * TILE_BYTES + soff, AH + gA, asz);
            cp16z(base + 1 * TILE_BYTES + soff, AL + gA, asz);
            size_t gB = (size_t)brow * DIM + k0 + seg * 8;
            cp16(base + 2 * TILE_BYTES + soff, WH + gB);
            cp16(base + 3 * TILE_BYTES + soff, WL + gB);
        }
        CP_COMMIT();
    };

    stage_load(0, 0);

    for (int kt = 0; kt < 16; ++kt) {
        int s = kt & 1;
        if (kt + 1 < 16) {
            stage_load(kt + 1, s ^ 1);
            asm volatile("cp.async.wait_group 1;");
        } else {
            asm volatile("cp.async.wait_group 0;");
        }
        __syncthreads();

        uint32_t uAh = sb + s * STAGE_BYTES;
        uint32_t uAl = uAh + TILE_BYTES;
        uint32_t uBh = uAh + 2 * TILE_BYTES;
        uint32_t uBl = uAh + 3 * TILE_BYTES;

        #pragma unroll
        for (int ks = 0; ks < 2; ++ks) {
            int kcol = ks * 16;
            uint32_t ah[2][4], al[2][4];
            #pragma unroll
            for (int mt = 0; mt < 2; ++mt) {
                int row = wm * 32 + mt * 16 + a_r;
                uint32_t off = (uint32_t)(row * 40 + kcol + a_c) * 2;
                LDMX4(ah[mt][0], ah[mt][1], ah[mt][2], ah[mt][3], uAh + off);
                LDMX4(al[mt][0], al[mt][1], al[mt][2], al[mt][3], uAl + off);
            }
            uint32_t bb[8][2];
            #pragma unroll
            for (int g = 0; g < 4; ++g) {
                int row = wn * 64 + g * 16 + b_r;
                uint32_t off = (uint32_t)(row * 40 + kcol + b_c) * 2;
                LDMX4(bb[2 * g][0], bb[2 * g][1], bb[2 * g + 1][0], bb[2 * g + 1][1], uBh + off);
            }
            #pragma unroll
            for (int mt = 0; mt < 2; ++mt)
                #pragma unroll
                for (int nt = 0; nt < 8; ++nt)
                    MMA16816(acc[mt][nt], ah[mt][0], ah[mt][1], ah[mt][2], ah[mt][3], bb[nt][0], bb[nt][1]);
            #pragma unroll
            for (int mt = 0; mt < 2; ++mt)
                #pragma unroll
                for (int nt = 0; nt < 8; ++nt)
                    MMA16816(acc[mt][nt], al[mt][0], al[mt][1], al[mt][2], al[mt][3], bb[nt][0], bb[nt][1]);
            #pragma unroll
            for (int g = 0; g < 4; ++g) {
                int row = wn * 64 + g * 16 + b_r;
                uint32_t off = (uint32_t)(row * 40 + kcol + b_c) * 2;
                LDMX4(bb[2 * g][0], bb[2 * g][1], bb[2 * g + 1][0], bb[2 * g + 1][1], uBl + off);
            }
            #pragma unroll
            for (int mt = 0; mt < 2; ++mt)
                #pragma unroll
                for (int nt = 0; nt < 8; ++nt)
                    MMA16816(acc[mt][nt], ah[mt][0], ah[mt][1], ah[mt][2], ah[mt][3], bb[nt][0], bb[nt][1]);
        }
        __syncthreads();
    }

    #pragma unroll
    for (int nt = 0; nt < 8; ++nt) {
        int c = bn + wn * 64 + nt * 8 + (lane & 3) * 2;
        float bb0 = bias[c], bb1 = bias[c + 1];
        #pragma unroll
        for (int mt = 0; mt < 2; ++mt) {
            int r0 = bm + wm * 32 + mt * 16 + (lane >> 2);
            #pragma unroll
            for (int half = 0; half < 2; ++half) {
                int r = r0 + half * 8;
                if (r >= M) continue;
                float v0 = acc[mt][nt][2 * half]     + bb0;
                float v1 = acc[mt][nt][2 * half + 1] + bb1;
                v0 = v0 >= 0.f ? v0 : NEG * v0;
                v1 = v1 >= 0.f ? v1 : NEG * v1;
                if (MODE == 0) {
                    __nv_bfloat162 hh = pk2(v0, v1);
                    float l0 = v0 - __bfloat162float(hh.x);
                    float l1 = v1 - __bfloat162float(hh.y);
                    *(__nv_bfloat162*)(g_hi2 + (size_t)r * DIM + c) = hh;
                    *(__nv_bfloat162*)(g_lo2 + (size_t)r * DIM + c) = pk2(l0, l1);
                } else {
                    *(float2*)(g_bufA + (size_t)r * DIM + c) = make_float2(v0, v1);
                }
            }
        }
    }
}

// ---------------- NodeNorm (in place on g_bufA) ----------------
__global__ void k_nodenorm() {
    int n = blockIdx.x;
    int t = threadIdx.x;   // 128
    float4* row = (float4*)(g_bufA + (size_t)n * DIM);
    float4 v = row[t];
    float s  = v.x + v.y + v.z + v.w;
    float sq = v.x * v.x + v.y * v.y + v.z * v.z + v.w * v.w;
    #pragma unroll
    for (int o = 16; o; o >>= 1) {
        s  += __shfl_down_sync(0xffffffffu, s, o);
        sq += __shfl_down_sync(0xffffffffu, sq, o);
    }
    __shared__ float ssum[4], ssq[4];
    int lane = t & 31, wid = t >> 5;
    if (lane == 0) { ssum[wid] = s; ssq[wid] = sq; }
    __syncthreads();
    float S = ssum[0] + ssum[1] + ssum[2] + ssum[3];
    float Q = ssq[0] + ssq[1] + ssq[2] + ssq[3];
    float mean = S * (1.0f / DIM);
    float var  = Q * (1.0f / DIM) - mean * mean;
    float inv  = rsqrtf(var + EPSF);
    v.x = (v.x - mean) * inv;
    v.y = (v.y - mean) * inv;
    v.z = (v.z - mean) * inv;
    v.w = (v.w - mean) * inv;
    row[t] = v;
}

// ---------------- BatchNorm ----------------
__global__ void k_zero512() {
    g_colsum[threadIdx.x] = 0.f;
    g_colsq[threadIdx.x] = 0.f;
}
__global__ void k_colstats() {
    int c = blockIdx.x * 128 + threadIdx.x;
    const int ROWS_PER = 782;
    int r0 = blockIdx.y * ROWS_PER;
    int r1 = r0 + ROWS_PER; if (r1 > NNODES) r1 = NNODES;
    float s = 0.f, q = 0.f;
    for (int r = r0; r < r1; ++r) {
        float v = g_bufA[(size_t)r * DIM + c];
        s += v; q += v * v;
    }
    atomicAdd(&g_colsum[c], s);
    atomicAdd(&g_colsq[c], q);
}
__global__ void k_bnfinal(const float* __restrict__ gamma, const float* __restrict__ beta) {
    int c = threadIdx.x;
    float mean = g_colsum[c] * (1.0f / NNODES);
    float var  = g_colsq[c] * (1.0f / NNODES) - mean * mean;
    float inv  = rsqrtf(var + EPSF);
    float sc   = gamma[c] * inv;
    g_scale[c] = sc;
    g_shift[c] = beta[c] - mean * sc;
}
__global__ void k_apply(float* __restrict__ xlocal, int layer) {
    int idx = blockIdx.x * blockDim.x + threadIdx.x;
    if (idx >= NNODES * (DIM / 4)) return;
    int n  = idx / (DIM / 4);
    int c4 = idx % (DIM / 4);
    float4 v = ((const float4*)g_bufA)[idx];
    int c = c4 * 4;
    v.x = v.x * g_scale[c + 0] + g_shift[c + 0];
    v.y = v.y * g_scale[c + 1] + g_shift[c + 1];
    v.z = v.z * g_scale[c + 2] + g_shift[c + 2];
    v.w = v.w * g_scale[c + 3] + g_shift[c + 3];
    ((float4*)(xlocal + (size_t)n * OUTD + (size_t)layer * DIM))[c4] = v;
}

// ---------------- global_add_pool: float4, 2-row unroll, inline graph-bound search ------
__global__ void k_pool(const float* __restrict__ xlocal, float* __restrict__ xglobal,
                       const int* __restrict__ batch) {
    int g  = blockIdx.x;
    int c4 = blockIdx.y * 128 + threadIdx.x;   // blockIdx.y in [0,4): 4*128 float4 = 2048 floats
    // per-block binary search for [r0, r1) of graph g (hidden across 2000 concurrent blocks)
    int lo = 0, hi = NNODES;
    while (lo < hi) { int mid = (lo + hi) >> 1; if (batch[mid] < g) lo = mid + 1; else hi = mid; }
    int r0 = lo;
    lo = r0; hi = NNODES;
    int g1 = g + 1;
    while (lo < hi) { int mid = (lo + hi) >> 1; if (batch[mid] < g1) lo = mid + 1; else hi = mid; }
    int r1 = lo;

    float4 s0 = make_float4(0.f, 0.f, 0.f, 0.f);
    float4 s1 = make_float4(0.f, 0.f, 0.f, 0.f);
    int r = r0;
    for (; r + 1 < r1; r += 2) {
        float4 a = __ldg((const float4*)(xlocal + (size_t)r * OUTD) + c4);
        float4 b = __ldg((const float4*)(xlocal + (size_t)(r + 1) * OUTD) + c4);
        s0.x += a.x; s0.y += a.y; s0.z += a.z; s0.w += a.w;
        s1.x += b.x; s1.y += b.y; s1.z += b.z; s1.w += b.w;
    }
    if (r < r1) {
        float4 a = __ldg((const float4*)(xlocal + (size_t)r * OUTD) + c4);
        s0.x += a.x; s0.y += a.y; s0.z += a.z; s0.w += a.w;
    }
    s0.x += s1.x; s0.y += s1.y; s0.z += s1.z; s0.w += s1.w;
    ((float4*)(xglobal + (size_t)g * OUTD))[c4] = s0;
}

// ---------------- driver ----------------
extern "C" void kernel_launch(void* const* d_in, const int* in_sizes, int n_in,
                              void* d_out, int out_size) {
    const float* x     = (const float*)d_in[0];
    const int*   ei    = (const int*)d_in[1];
    const int*   batch = (const int*)d_in[2];
    const float* W1    = (const float*)d_in[3];
    const float* b1    = (const float*)d_in[4];
    const float* W2    = (const float*)d_in[5];
    const float* b2    = (const float*)d_in[6];
    const float* gamma = (const float*)d_in[7];
    const float* beta  = (const float*)d_in[8];

    float* out     = (float*)d_out;
    float* xglobal = out;
    float* xlocal  = out + (size_t)NGRAPHS * OUTD;

    cudaFuncSetAttribute(k_mma<0>, cudaFuncAttributeMaxDynamicSharedMemorySize, SMEM_TOTAL);
    cudaFuncSetAttribute(k_mma<1>, cudaFuncAttributeMaxDynamicSharedMemorySize, SMEM_TOTAL);

    k_wconv_all<<<dim3(16, 16, 8), dim3(32, 32)>>>(W1, W2);   // also zeroes g_cur
    k_count<<<(NEDGES + 255) / 256, 256>>>(ei);
    k_scan<<<1, 1024>>>();
    k_fill<<<(NEDGES + 255) / 256, 256>>>(ei);

    dim3 mma_grid(4, (NNODES + 127) / 128);

    for (int l = 0; l < NLAYERS; ++l) {
        const float* h = (l == 0) ? x : (xlocal + (size_t)(l - 1) * DIM);
        int ldh = (l == 0) ? DIM : OUTD;
        k_aggregate<<<NNODES, 128>>>(h, ldh);
        k_mma<0><<<mma_grid, 256, SMEM_TOTAL>>>(l, b1 + (size_t)l * DIM, NNODES);
        k_mma<1><<<mma_grid, 256, SMEM_TOTAL>>>(l, b2 + (size_t)l * DIM, NNODES);
        k_nodenorm<<<NNODES, 128>>>();
        k_zero512<<<1, 512>>>();
        k_colstats<<<dim3(4, 64), 128>>>();
        k_bnfinal<<<1, 512>>>(gamma + (size_t)l * DIM, beta + (size_t)l * DIM);
        k_apply<<<(NNODES * (DIM / 4) + 255) / 256, 256>>>(xlocal, l);
    }

    k_pool<<<dim3(NGRAPHS, 4), 128>>>(xlocal, xglobal, batch);
}

// round 16
// speedup vs baseline: 1.1515x; 1.0495x over previous
#include <cuda_runtime.h>
#include <cuda_bf16.h>
#include <cstdint>

#define NNODES 50000
#define NEDGES 400000
#define DIM 512
#define NLAYERS 4
#define NGRAPHS 500
#define OUTD 2048
#define EPSF 1e-5f
#define NEG 0.01f

// ---------------- scratch ----------------
__device__ float g_bufA[(size_t)NNODES * DIM];
__device__ __nv_bfloat16 g_hi[(size_t)NNODES * DIM];    // GEMM1 input (from aggregate)
__device__ __nv_bfloat16 g_lo[(size_t)NNODES * DIM];
__device__ __nv_bfloat16 g_hi2[(size_t)NNODES * DIM];   // GEMM1 output / GEMM2 input
__device__ __nv_bfloat16 g_lo2[(size_t)NNODES * DIM];
__device__ __nv_bfloat16 g_wt1h[NLAYERS * DIM * DIM], g_wt1l[NLAYERS * DIM * DIM];
__device__ __nv_bfloat16 g_wt2h[NLAYERS * DIM * DIM], g_wt2l[NLAYERS * DIM * DIM];
__device__ int   g_off[NNODES + 1];
__device__ int   g_cur[NNODES];
__device__ int   g_esrc[NEDGES];
__device__ float g_colsum[DIM];
__device__ float g_colsq[DIM];
__device__ float g_scale[DIM];
__device__ float g_shift[DIM];
__device__ int   g_gstart[NGRAPHS + 1];

__device__ __forceinline__ uint32_t smem_u32(const void* p) {
    uint32_t a;
    asm("{ .reg .u64 t; cvta.to.shared.u64 t, %1; cvt.u32.u64 %0, t; }" : "=r"(a) : "l"(p));
    return a;
}

#define LDMX4(r0, r1, r2, r3, addr) \
    asm volatile("ldmatrix.sync.aligned.m8n8.x4.shared.b16 {%0,%1,%2,%3}, [%4];" \
        : "=r"(r0), "=r"(r1), "=r"(r2), "=r"(r3) : "r"(addr))

#define MMA16816(d, a0, a1, a2, a3, b0, b1) \
    asm volatile("mma.sync.aligned.m16n8k16.row.col.f32.bf16.bf16.f32 " \
        "{%0,%1,%2,%3}, {%4,%5,%6,%7}, {%8,%9}, {%0,%1,%2,%3};" \
        : "+f"((d)[0]), "+f"((d)[1]), "+f"((d)[2]), "+f"((d)[3]) \
        : "r"(a0), "r"(a1), "r"(a2), "r"(a3), "r"(b0), "r"(b1))

__device__ __forceinline__ void cp16z(uint32_t dst, const void* src, int srcsize) {
    asm volatile("cp.async.cg.shared.global [%0], [%1], 16, %2;" :: "r"(dst), "l"(src), "r"(srcsize));
}
__device__ __forceinline__ void cp16(uint32_t dst, const void* src) {
    asm volatile("cp.async.cg.shared.global [%0], [%1], 16;" :: "r"(dst), "l"(src));
}
#define CP_COMMIT() asm volatile("cp.async.commit_group;")

__device__ __forceinline__ __nv_bfloat162 pk2(float a, float b) {
    __nv_bfloat162 r; r.x = __float2bfloat16(a); r.y = __float2bfloat16(b); return r;
}

// ---------------- weights conversion + g_cur zeroing (launch #1) ----------------
__global__ void k_wconv_all(const float* __restrict__ W1, const float* __restrict__ W2) {
    int gb = (blockIdx.z * gridDim.y + blockIdx.y) * gridDim.x + blockIdx.x;
    int gidx = gb * 1024 + threadIdx.y * 32 + threadIdx.x;
    if (gidx < NNODES) g_cur[gidx] = 0;

    __shared__ float tile[32][33];
    int zc = blockIdx.z;
    int l = zc >> 1, which = zc & 1;
    const float* W = ((which == 0) ? W1 : W2) + (size_t)l * DIM * DIM;
    int k0 = blockIdx.y * 32, n0 = blockIdx.x * 32;
    int tx = threadIdx.x, ty = threadIdx.y;
    tile[ty][tx] = W[(size_t)(k0 + ty) * DIM + n0 + tx];
    __syncthreads();
    float v = tile[tx][ty];
    __nv_bfloat16 h = __float2bfloat16(v);
    float lo = v - __bfloat162float(h);
    size_t idx = (size_t)l * DIM * DIM + (size_t)(n0 + ty) * DIM + k0 + tx;
    if (which == 0) { g_wt1h[idx] = h; g_wt1l[idx] = __float2bfloat16(lo); }
    else            { g_wt2h[idx] = h; g_wt2l[idx] = __float2bfloat16(lo); }
}

// ---------------- CSR build ----------------
__global__ void k_count(const int* __restrict__ ei) {
    int e = blockIdx.x * blockDim.x + threadIdx.x;
    if (e < NEDGES) atomicAdd(&g_cur[ei[NEDGES + e]], 1);
}
__global__ void k_scan() {
    __shared__ int wsum[32];
    __shared__ int carry_s;
    int tid = threadIdx.x, lane = tid & 31, wid = tid >> 5;
    if (tid == 0) carry_s = 0;
    __syncthreads();
    for (int base = 0; base < NNODES; base += 1024) {
        int i = base + tid;
        int orig = (i < NNODES) ? g_cur[i] : 0;
        int v = orig;
        #pragma unroll
        for (int o = 1; o < 32; o <<= 1) {
            int t = __shfl_up_sync(0xffffffffu, v, o);
            if (lane >= o) v += t;
        }
        if (lane == 31) wsum[wid] = v;
        __syncthreads();
        if (wid == 0) {
            int s = wsum[lane];
            #pragma unroll
            for (int o = 1; o < 32; o <<= 1) {
                int t = __shfl_up_sync(0xffffffffu, s, o);
                if (lane >= o) s += t;
            }
            wsum[lane] = s;
        }
        __syncthreads();
        int prev = (wid > 0) ? wsum[wid - 1] : 0;
        int incl = carry_s + prev + v;
        int excl = incl - orig;
        if (i < NNODES) { g_off[i] = excl; g_cur[i] = excl; }
        __syncthreads();
        if (tid == 1023) carry_s = incl;
        __syncthreads();
    }
    if (threadIdx.x == 0) g_off[NNODES] = carry_s;
}
__global__ void k_fill(const int* __restrict__ ei) {
    int e = blockIdx.x * blockDim.x + threadIdx.x;
    if (e < NEDGES) {
        int p = atomicAdd(&g_cur[ei[NEDGES + e]], 1);
        g_esrc[p] = ei[e];
    }
}
__global__ void k_gstart(const int* __restrict__ batch) {
    int g = blockIdx.x * blockDim.x + threadIdx.x;
    if (g > NGRAPHS) return;
    int lo = 0, hi = NNODES;
    while (lo < hi) {
        int mid = (lo + hi) >> 1;
        if (batch[mid] < g) lo = mid + 1; else hi = mid;
    }
    g_gstart[g] = lo;
}

// ---------------- aggregation -> split bf16 into g_hi/g_lo ----------------
__global__ void k_aggregate(const float* __restrict__ h, int ldh) {
    int n = blockIdx.x;
    int t = threadIdx.x;   // 128 threads * 4 cols
    float4 acc = __ldg((const float4*)(h + (size_t)n * ldh) + t);
    int e0 = g_off[n], e1 = g_off[n + 1];
    for (int e = e0; e < e1; ++e) {
        int s = g_esrc[e];
        float4 v = __ldg((const float4*)(h + (size_t)s * ldh) + t);
        acc.x += v.x; acc.y += v.y; acc.z += v.z; acc.w += v.w;
    }
    __nv_bfloat162 h01 = pk2(acc.x, acc.y), h23 = pk2(acc.z, acc.w);
    float lx = acc.x - __bfloat162float(h01.x);
    float ly = acc.y - __bfloat162float(h01.y);
    float lz = acc.z - __bfloat162float(h23.x);
    float lw = acc.w - __bfloat162float(h23.y);
    __nv_bfloat162* hp = (__nv_bfloat162*)(g_hi + (size_t)n * DIM);
    __nv_bfloat162* lp = (__nv_bfloat162*)(g_lo + (size_t)n * DIM);
    hp[2 * t] = h01; hp[2 * t + 1] = h23;
    lp[2 * t] = pk2(lx, ly); lp[2 * t + 1] = pk2(lz, lw);
}

// ---------------- mma.sync GEMM (byte-identical to round-12 passing version) ----------
#define TILE_BYTES 10240          // 128*40*2
#define STAGE_BYTES 40960
#define SMEM_TOTAL 81920

template <int MODE>
__global__ void __launch_bounds__(256, 2) k_mma(int layer, const float* __restrict__ bias, int M) {
    extern __shared__ char smem[];
    uint32_t sb = smem_u32(smem);

    size_t wo = (size_t)layer * DIM * DIM;
    const __nv_bfloat16* AH = (MODE == 0) ? g_hi : g_hi2;
    const __nv_bfloat16* AL = (MODE == 0) ? g_lo : g_lo2;
    const __nv_bfloat16* WH = ((MODE == 0) ? g_wt1h : g_wt2h) + wo;
    const __nv_bfloat16* WL = ((MODE == 0) ? g_wt1l : g_wt2l) + wo;

    int tid  = threadIdx.x;
    int lane = tid & 31;
    int wid  = tid >> 5;
    int wm   = wid & 3;
    int wn   = wid >> 2;
    int bm   = blockIdx.y * 128;
    int bn   = blockIdx.x * 128;

    float acc[2][8][4];
    #pragma unroll
    for (int i = 0; i < 2; ++i)
        #pragma unroll
        for (int j = 0; j < 8; ++j)
            #pragma unroll
            for (int q = 0; q < 4; ++q) acc[i][j][q] = 0.f;

    int lrow = tid >> 1;
    int lseg = (tid & 1) * 2;

    int a_r = (lane & 7) + ((lane >> 3) & 1) * 8;
    int a_c = (lane >> 4) * 8;
    int b_r = (lane & 7) + (lane >> 4) * 8;
    int b_c = ((lane >> 3) & 1) * 8;

    int gr = bm + lrow;
    int asz = (gr < M) ? 16 : 0;
    int grc = (gr < M) ? gr : (M - 1);
    int brow = bn + lrow;

    auto stage_load = [&](int kt, int s) {
        int k0 = kt * 32;
        uint32_t base = sb + s * STAGE_BYTES;
        #pragma unroll
        for (int j = 0; j < 2; ++j) {
            int seg = lseg + j;
            uint32_t soff = (uint32_t)(lrow * 40 + seg * 8) * 2;
            size_t gA = (size_t)grc * DIM + k0 + seg * 8;
            cp16z(base + 0 * TILE_BYTES + soff, AH + gA, asz);
            cp16z(base + 1 * TILE_BYTES + soff, AL + gA, asz);
            size_t gB = (size_t)brow * DIM + k0 + seg * 8;
            cp16(base + 2 * TILE_BYTES + soff, WH + gB);
            cp16(base + 3 * TILE_BYTES + soff, WL + gB);
        }
        CP_COMMIT();
    };

    stage_load(0, 0);

    for (int kt = 0; kt < 16; ++kt) {
        int s = kt & 1;
        if (kt + 1 < 16) {
            stage_load(kt + 1, s ^ 1);
            asm volatile("cp.async.wait_group 1;");
        } else {
            asm volatile("cp.async.wait_group 0;");
        }
        __syncthreads();

        uint32_t uAh = sb + s * STAGE_BYTES;
        uint32_t uAl = uAh + TILE_BYTES;
        uint32_t uBh = uAh + 2 * TILE_BYTES;
        uint32_t uBl = uAh + 3 * TILE_BYTES;

        #pragma unroll
        for (int ks = 0; ks < 2; ++ks) {
            int kcol = ks * 16;
            uint32_t ah[2][4], al[2][4];
            #pragma unroll
            for (int mt = 0; mt < 2; ++mt) {
                int row = wm * 32 + mt * 16 + a_r;
                uint32_t off = (uint32_t)(row * 40 + kcol + a_c) * 2;
                LDMX4(ah[mt][0], ah[mt][1], ah[mt][2], ah[mt][3], uAh + off);
                LDMX4(al[mt][0], al[mt][1], al[mt][2], al[mt][3], uAl + off);
            }
            uint32_t bb[8][2];
            #pragma unroll
            for (int g = 0; g < 4; ++g) {
                int row = wn * 64 + g * 16 + b_r;
                uint32_t off = (uint32_t)(row * 40 + kcol + b_c) * 2;
                LDMX4(bb[2 * g][0], bb[2 * g][1], bb[2 * g + 1][0], bb[2 * g + 1][1], uBh + off);
            }
            #pragma unroll
            for (int mt = 0; mt < 2; ++mt)
                #pragma unroll
                for (int nt = 0; nt < 8; ++nt)
                    MMA16816(acc[mt][nt], ah[mt][0], ah[mt][1], ah[mt][2], ah[mt][3], bb[nt][0], bb[nt][1]);
            #pragma unroll
            for (int mt = 0; mt < 2; ++mt)
                #pragma unroll
                for (int nt = 0; nt < 8; ++nt)
                    MMA16816(acc[mt][nt], al[mt][0], al[mt][1], al[mt][2], al[mt][3], bb[nt][0], bb[nt][1]);
            #pragma unroll
            for (int g = 0; g < 4; ++g) {
                int row = wn * 64 + g * 16 + b_r;
                uint32_t off = (uint32_t)(row * 40 + kcol + b_c) * 2;
                LDMX4(bb[2 * g][0], bb[2 * g][1], bb[2 * g + 1][0], bb[2 * g + 1][1], uBl + off);
            }
            #pragma unroll
            for (int mt = 0; mt < 2; ++mt)
                #pragma unroll
                for (int nt = 0; nt < 8; ++nt)
                    MMA16816(acc[mt][nt], ah[mt][0], ah[mt][1], ah[mt][2], ah[mt][3], bb[nt][0], bb[nt][1]);
        }
        __syncthreads();
    }

    #pragma unroll
    for (int nt = 0; nt < 8; ++nt) {
        int c = bn + wn * 64 + nt * 8 + (lane & 3) * 2;
        float bb0 = bias[c], bb1 = bias[c + 1];
        #pragma unroll
        for (int mt = 0; mt < 2; ++mt) {
            int r0 = bm + wm * 32 + mt * 16 + (lane >> 2);
            #pragma unroll
            for (int half = 0; half < 2; ++half) {
                int r = r0 + half * 8;
                if (r >= M) continue;
                float v0 = acc[mt][nt][2 * half]     + bb0;
                float v1 = acc[mt][nt][2 * half + 1] + bb1;
                v0 = v0 >= 0.f ? v0 : NEG * v0;
                v1 = v1 >= 0.f ? v1 : NEG * v1;
                if (MODE == 0) {
                    __nv_bfloat162 hh = pk2(v0, v1);
                    float l0 = v0 - __bfloat162float(hh.x);
                    float l1 = v1 - __bfloat162float(hh.y);
                    *(__nv_bfloat162*)(g_hi2 + (size_t)r * DIM + c) = hh;
                    *(__nv_bfloat162*)(g_lo2 + (size_t)r * DIM + c) = pk2(l0, l1);
                } else {
                    *(float2*)(g_bufA + (size_t)r * DIM + c) = make_float2(v0, v1);
                }
            }
        }
    }
}

// ---------------- NodeNorm (in place on g_bufA) ----------------
__global__ void k_nodenorm() {
    int n = blockIdx.x;
    int t = threadIdx.x;   // 128
    float4* row = (float4*)(g_bufA + (size_t)n * DIM);
    float4 v = row[t];
    float s  = v.x + v.y + v.z + v.w;
    float sq = v.x * v.x + v.y * v.y + v.z * v.z + v.w * v.w;
    #pragma unroll
    for (int o = 16; o; o >>= 1) {
        s  += __shfl_down_sync(0xffffffffu, s, o);
        sq += __shfl_down_sync(0xffffffffu, sq, o);
    }
    __shared__ float ssum[4], ssq[4];
    int lane = t & 31, wid = t >> 5;
    if (lane == 0) { ssum[wid] = s; ssq[wid] = sq; }
    __syncthreads();
    float S = ssum[0] + ssum[1] + ssum[2] + ssum[3];
    float Q = ssq[0] + ssq[1] + ssq[2] + ssq[3];
    float mean = S * (1.0f / DIM);
    float var  = Q * (1.0f / DIM) - mean * mean;
    float inv  = rsqrtf(var + EPSF);
    v.x = (v.x - mean) * inv;
    v.y = (v.y - mean) * inv;
    v.z = (v.z - mean) * inv;
    v.w = (v.w - mean) * inv;
    row[t] = v;
}

// ---------------- BatchNorm ----------------
__global__ void k_zero512() {
    g_colsum[threadIdx.x] = 0.f;
    g_colsq[threadIdx.x] = 0.f;
}
// 4x more row-blocks than before: 131K resident threads instead of 32K -> MLP-bound fix
__global__ void k_colstats() {
    int c = blockIdx.x * 128 + threadIdx.x;       // blockIdx.x in [0,4)
    const int ROWS_PER = 196;                     // 196 * 256 >= 50000
    int r0 = blockIdx.y * ROWS_PER;
    int r1 = r0 + ROWS_PER; if (r1 > NNODES) r1 = NNODES;
    float s = 0.f, q = 0.f;
    for (int r = r0; r < r1; ++r) {
        float v = g_bufA[(size_t)r * DIM + c];
        s += v; q += v * v;
    }
    atomicAdd(&g_colsum[c], s);
    atomicAdd(&g_colsq[c], q);
}
__global__ void k_bnfinal(const float* __restrict__ gamma, const float* __restrict__ beta) {
    int c = threadIdx.x;
    float mean = g_colsum[c] * (1.0f / NNODES);
    float var  = g_colsq[c] * (1.0f / NNODES) - mean * mean;
    float inv  = rsqrtf(var + EPSF);
    float sc   = gamma[c] * inv;
    g_scale[c] = sc;
    g_shift[c] = beta[c] - mean * sc;
}
__global__ void k_apply(float* __restrict__ xlocal, int layer) {
    int idx = blockIdx.x * blockDim.x + threadIdx.x;
    if (idx >= NNODES * (DIM / 4)) return;
    int n  = idx / (DIM / 4);
    int c4 = idx % (DIM / 4);
    float4 v = ((const float4*)g_bufA)[idx];
    int c = c4 * 4;
    v.x = v.x * g_scale[c + 0] + g_shift[c + 0];
    v.y = v.y * g_scale[c + 1] + g_shift[c + 1];
    v.z = v.z * g_scale[c + 2] + g_shift[c + 2];
    v.w = v.w * g_scale[c + 3] + g_shift[c + 3];
    ((float4*)(xlocal + (size_t)n * OUTD + (size_t)layer * DIM))[c4] = v;
}
__global__ void k_pool(const float* __restrict__ xlocal, float* __restrict__ xglobal) {
    int g = blockIdx.x;
    int c = blockIdx.y * 128 + threadIdx.x;
    int r0 = g_gstart[g], r1 = g_gstart[g + 1];
    float s = 0.f;
    for (int r = r0; r < r1; ++r) s += xlocal[(size_t)r * OUTD + c];
    xglobal[(size_t)g * OUTD + c] = s;
}

// ---------------- driver ----------------
extern "C" void kernel_launch(void* const* d_in, const int* in_sizes, int n_in,
                              void* d_out, int out_size) {
    const float* x     = (const float*)d_in[0];
    const int*   ei    = (const int*)d_in[1];
    const int*   batch = (const int*)d_in[2];
    const float* W1    = (const float*)d_in[3];
    const float* b1    = (const float*)d_in[4];
    const float* W2    = (const float*)d_in[5];
    const float* b2    = (const float*)d_in[6];
    const float* gamma = (const float*)d_in[7];
    const float* beta  = (const float*)d_in[8];

    float* out     = (float*)d_out;
    float* xglobal = out;
    float* xlocal  = out + (size_t)NGRAPHS * OUTD;

    cudaFuncSetAttribute(k_mma<0>, cudaFuncAttributeMaxDynamicSharedMemorySize, SMEM_TOTAL);
    cudaFuncSetAttribute(k_mma<1>, cudaFuncAttributeMaxDynamicSharedMemorySize, SMEM_TOTAL);

    k_wconv_all<<<dim3(16, 16, 8), dim3(32, 32)>>>(W1, W2);   // also zeroes g_cur
    k_count<<<(NEDGES + 255) / 256, 256>>>(ei);
    k_scan<<<1, 1024>>>();
    k_fill<<<(NEDGES + 255) / 256, 256>>>(ei);

    dim3 mma_grid(4, (NNODES + 127) / 128);

    for (int l = 0; l < NLAYERS; ++l) {
        const float* h = (l == 0) ? x : (xlocal + (size_t)(l - 1) * DIM);
        int ldh = (l == 0) ? DIM : OUTD;
        k_aggregate<<<NNODES, 128>>>(h, ldh);
        k_mma<0><<<mma_grid, 256, SMEM_TOTAL>>>(l, b1 + (size_t)l * DIM, NNODES);
        k_mma<1><<<mma_grid, 256, SMEM_TOTAL>>>(l, b2 + (size_t)l * DIM, NNODES);
        k_nodenorm<<<NNODES, 128>>>();
        k_zero512<<<1, 512>>>();
        k_colstats<<<dim3(4, 256), 128>>>();
        k_bnfinal<<<1, 512>>>(gamma + (size_t)l * DIM, beta + (size_t)l * DIM);
        k_apply<<<(NNODES * (DIM / 4) + 255) / 256, 256>>>(xlocal, l);
    }

    k_gstart<<<2, 256>>>(batch);
    k_pool<<<dim3(NGRAPHS, 16), 128>>>(xlocal, xglobal);
}